// round 12
// baseline (speedup 1.0000x reference)
#include <cuda_runtime.h>
#include <cuda_bf16.h>

#define T_  1024
#define H_  2048
#define I_  4096
#define E_  8
#define GS  32

// ---------------- static device scratch ----------------
__device__ __nv_bfloat16 g_gbuf[(size_t)E_ * T_ * I_];   // g (bf16, as materialized by reference)
__device__ float g_oslot[(size_t)T_ * 2 * H_];           // per-slot outputs (bf16-valued, stored f32)
__device__ float g_wts[T_ * 2];
__device__ int   g_cnt[E_];
__device__ int   g_entries[E_ * T_];

// content-probed bindings + dtype flags
__device__ const void* g_x;
__device__ const int*  g_w2s;
__device__ const float* g_gw;
__device__ const void* g_w2b;
__device__ int g_xf32, g_b13f32, g_b2f32;

// fp4(e2m1) nibble * 2^(s-127), exact, as f32 bits.
__device__ __forceinline__ float dq(int nib, int s) {
    int mag = nib & 7;
    int sgn = (nib & 8) << 28;
    if (s == 0 || mag == 0) return __int_as_float(sgn);
    int ebits, mant;
    if (mag == 1) {
        if (s == 1) return __int_as_float(sgn | 0x00400000);
        ebits = s - 1; mant = 0;
    } else {
        ebits = s + (mag >> 1) - 1;
        mant  = (mag & 1) << 22;
    }
    return __int_as_float(sgn | (ebits << 23) | mant);
}

__device__ int looks_f32(const unsigned* u, int n) {
    int small = 0;
    for (int i = 0; i < n; i++) {
        unsigned e = (u[i] >> 7) & 0xFF;
        if (e < 64) small++;
    }
    return small > (n >> 4);
}

__device__ __forceinline__ float rb(float v) {   // round f32 -> bf16 -> f32
    return __bfloat162float(__float2bfloat16(v));
}

// ---------------- K-1: probe ----------------
__global__ void k_probe(const void* a2m0, const void* a2m1,
                        const void* a16k0, const void* a16k1,
                        const void* w13b) {
    if (threadIdx.x != 0) return;
    const unsigned* u = (const unsigned*)a2m0;
    bool allsmall = true;
    for (int i = 0; i < 4096; i++) if (u[i] >= 128u) { allsmall = false; break; }
    const void* xptr; const void* w2sptr;
    if (allsmall) { w2sptr = a2m0; xptr = a2m1; }
    else          { xptr = a2m0;  w2sptr = a2m1; }
    g_x = xptr; g_w2s = (const int*)w2sptr;
    const float* f = (const float*)a16k0;
    bool big = false;
    for (int i = 0; i < 4096; i++) if (fabsf(f[i]) >= 1.f) { big = true; break; }
    const void* gwp; const void* w2bp;
    if (big) { w2bp = a16k0; gwp = a16k1; }
    else     { gwp = a16k0;  w2bp = a16k1; }
    g_gw = (const float*)gwp; g_w2b = w2bp;
    g_xf32   = looks_f32((const unsigned*)xptr, 256);
    g_b13f32 = looks_f32((const unsigned*)w13b, 256);
    g_b2f32  = looks_f32((const unsigned*)w2bp, 256);
    for (int e = 0; e < E_; e++) g_cnt[e] = 0;
}

// ---------------- K1: gating (full f32 logits GEMM) ----------------
__global__ void __launch_bounds__(256) k_gate() {
    const float* gw = g_gw;
    int xf = g_xf32;
    const float* xf32 = (const float*)g_x;
    const __nv_bfloat16* xb = (const __nv_bfloat16*)g_x;
    int warp = threadIdx.x >> 5, lane = threadIdx.x & 31;
    int t = blockIdx.x * 8 + warp;
    float acc[E_];
#pragma unroll
    for (int e = 0; e < E_; e++) acc[e] = 0.f;
    for (int h = lane; h < H_; h += 32) {
        float xv = xf ? xf32[(size_t)t * H_ + h]
                      : __bfloat162float(xb[(size_t)t * H_ + h]);
#pragma unroll
        for (int e = 0; e < E_; e++) acc[e] += xv * gw[e * H_ + h];
    }
#pragma unroll
    for (int e = 0; e < E_; e++) {
#pragma unroll
        for (int off = 16; off > 0; off >>= 1)
            acc[e] += __shfl_xor_sync(0xffffffffu, acc[e], off);
    }
    if (lane == 0) {
        float m = acc[0];
#pragma unroll
        for (int e = 1; e < E_; e++) m = fmaxf(m, acc[e]);
        float p[E_], s = 0.f;
#pragma unroll
        for (int e = 0; e < E_; e++) { p[e] = expf(acc[e] - m); s += p[e]; }
#pragma unroll
        for (int e = 0; e < E_; e++) p[e] /= s;
        int i0 = 0; float p0v = p[0];
#pragma unroll
        for (int e = 1; e < E_; e++) if (p[e] > p0v) { p0v = p[e]; i0 = e; }
        int i1 = -1; float p1v = -1.f;
#pragma unroll
        for (int e = 0; e < E_; e++) {
            if (e == i0) continue;
            if (p[e] > p1v) { p1v = p[e]; i1 = e; }
        }
        float ws = p0v + p1v;
        g_wts[t * 2 + 0] = p0v / ws;
        g_wts[t * 2 + 1] = p1v / ws;
        int pos = atomicAdd(&g_cnt[i0], 1);
        g_entries[i0 * T_ + pos] = (t << 1);
        pos = atomicAdd(&g_cnt[i1], 1);
        g_entries[i1 * T_ + pos] = (t << 1) | 1;
    }
}

// ---------------- K2: routed up projection ----------------
__global__ void __launch_bounds__(256) k_up(const int* __restrict__ w1,
                                            const int* __restrict__ w3,
                                            const int* __restrict__ w13s,
                                            const void* __restrict__ w13b) {
    int e = blockIdx.z;
    int cnt = g_cnt[e];
    int m0 = blockIdx.y * 32;
    if (m0 >= cnt) return;
    int i0 = blockIdx.x * 64;

    __shared__ float Xs[64][34];
    __shared__ float W1s[64][68];
    __shared__ float W3s[64][68];
    __shared__ int stok[32];

    int tid = threadIdx.x;
    if (tid < 32) {
        int slot = m0 + tid;
        stok[tid] = (slot < cnt) ? (g_entries[e * T_ + slot] >> 1) : -1;
    }
    __syncthreads();

    int xf = g_xf32;
    int tx = tid & 15, ty = tid >> 4;
    float acc1[2][4], acc3[2][4];
#pragma unroll
    for (int a = 0; a < 2; a++)
#pragma unroll
        for (int b = 0; b < 4; b++) { acc1[a][b] = 0.f; acc3[a][b] = 0.f; }

    int xtok_i = tid >> 3;
    int xk = (tid & 7) * 8;
    int xt = stok[xtok_i];
    int wr = tid >> 2;
    int wq = tid & 3;
    long wrow1 = ((long)e * I_ + i0 + wr) * (H_ / 2);
    long srow1 = ((long)e * 2 * I_ + i0 + wr) * (H_ / GS);
    long srow3 = ((long)e * 2 * I_ + I_ + i0 + wr) * (H_ / GS);

    for (int kc = 0; kc < H_ / 64; kc++) {
        float xv8[8];
        if (xt >= 0) {
            if (xf) {
                const float4* p = (const float4*)((const float*)g_x +
                                  (size_t)xt * H_ + kc * 64 + xk);
                float4 a = p[0], b = p[1];
                xv8[0] = a.x; xv8[1] = a.y; xv8[2] = a.z; xv8[3] = a.w;
                xv8[4] = b.x; xv8[5] = b.y; xv8[6] = b.z; xv8[7] = b.w;
            } else {
                uint4 v = *(const uint4*)((const __nv_bfloat16*)g_x +
                          (size_t)xt * H_ + kc * 64 + xk);
                const __nv_bfloat16* xbp = (const __nv_bfloat16*)&v;
#pragma unroll
                for (int j = 0; j < 8; j++) xv8[j] = __bfloat162float(xbp[j]);
            }
        } else {
#pragma unroll
            for (int j = 0; j < 8; j++) xv8[j] = 0.f;
        }
#pragma unroll
        for (int j = 0; j < 8; j++) Xs[xk + j][xtok_i] = xv8[j];

        {
            long base = wrow1 + kc * 32 + wq * 8;
            int4 p0 = *(const int4*)(w1 + base);
            int4 p1 = *(const int4*)(w1 + base + 4);
            int s1 = w13s[srow1 + kc * 2 + (wq >> 1)];
            int vals[8] = {p0.x, p0.y, p0.z, p0.w, p1.x, p1.y, p1.z, p1.w};
#pragma unroll
            for (int m2 = 0; m2 < 8; m2++) {
                int v = vals[m2];
                W1s[wq * 16 + 2 * m2 + 0][wr] = dq(v & 15, s1);
                W1s[wq * 16 + 2 * m2 + 1][wr] = dq((v >> 4) & 15, s1);
            }
            int4 q0 = *(const int4*)(w3 + base);
            int4 q1 = *(const int4*)(w3 + base + 4);
            int s3 = w13s[srow3 + kc * 2 + (wq >> 1)];
            int vals3[8] = {q0.x, q0.y, q0.z, q0.w, q1.x, q1.y, q1.z, q1.w};
#pragma unroll
            for (int m2 = 0; m2 < 8; m2++) {
                int v = vals3[m2];
                W3s[wq * 16 + 2 * m2 + 0][wr] = dq(v & 15, s3);
                W3s[wq * 16 + 2 * m2 + 1][wr] = dq((v >> 4) & 15, s3);
            }
        }
        __syncthreads();

#pragma unroll 16
        for (int k = 0; k < 64; k++) {
            float2 a = *(const float2*)&Xs[k][ty * 2];
            float4 b1 = *(const float4*)&W1s[k][tx * 4];
            float4 b3 = *(const float4*)&W3s[k][tx * 4];
            acc1[0][0] += a.x * b1.x; acc1[0][1] += a.x * b1.y;
            acc1[0][2] += a.x * b1.z; acc1[0][3] += a.x * b1.w;
            acc1[1][0] += a.y * b1.x; acc1[1][1] += a.y * b1.y;
            acc1[1][2] += a.y * b1.z; acc1[1][3] += a.y * b1.w;
            acc3[0][0] += a.x * b3.x; acc3[0][1] += a.x * b3.y;
            acc3[0][2] += a.x * b3.z; acc3[0][3] += a.x * b3.w;
            acc3[1][0] += a.y * b3.x; acc3[1][1] += a.y * b3.y;
            acc3[1][2] += a.y * b3.z; acc3[1][3] += a.y * b3.w;
        }
        __syncthreads();
    }

    int bf32 = g_b13f32;
    const float* bpf = (const float*)w13b + (long)e * 2 * I_;
    const __nv_bfloat16* bph = (const __nv_bfloat16*)w13b + (long)e * 2 * I_;
#pragma unroll
    for (int jt = 0; jt < 2; jt++) {
        int slot = m0 + ty * 2 + jt;
        if (slot >= cnt) continue;
        size_t gbase = ((size_t)e * T_ + slot) * I_;
#pragma unroll
        for (int ji = 0; ji < 4; ji++) {
            int i = i0 + tx * 4 + ji;
            float b1v = bf32 ? bpf[i]      : __bfloat162float(bph[i]);
            float b3v = bf32 ? bpf[I_ + i] : __bfloat162float(bph[I_ + i]);
            // Per-op bf16 chain; sigmoid via XLA logistic_expander exp-form:
            //   logistic(x) = 1 / (1 + exp(-x)), each HLO op rounding to bf16.
            float h1 = rb(acc1[jt][ji]);        // einsum output -> bf16
            h1 = rb(h1 + b1v);                  // + bias -> bf16
            float h3 = rb(acc3[jt][ji]);
            h3 = rb(h3 + b3v);
            float em  = rb(expf(-h1));          // exp(-x) -> bf16
            float den = rb(1.f + em);           // 1 + . -> bf16
            float sg  = rb(1.f / den);          // divide -> bf16
            float sl  = rb(h1 * sg);            // x * sigmoid(x) -> bf16
            g_gbuf[gbase + i] = __float2bfloat16(sl * h3);   // g -> bf16
        }
    }
}

// ---------------- K3: routed down projection ----------------
__global__ void __launch_bounds__(256) k_down(const int* __restrict__ w2) {
    const int* w2s = g_w2s;
    int e = blockIdx.z;
    int cnt = g_cnt[e];
    int m0 = blockIdx.y * 32;
    if (m0 >= cnt) return;
    int h0 = blockIdx.x * 64;

    __shared__ float Gs[64][34];
    __shared__ float Ws[64][68];
    __shared__ int sent[32];

    int tid = threadIdx.x;
    if (tid < 32) {
        int slot = m0 + tid;
        sent[tid] = (slot < cnt) ? g_entries[e * T_ + slot] : -1;
    }
    __syncthreads();

    int tx = tid & 15, ty = tid >> 4;
    float acc[2][4];
#pragma unroll
    for (int a = 0; a < 2; a++)
#pragma unroll
        for (int b = 0; b < 4; b++) acc[a][b] = 0.f;

    int gslot_i = tid >> 3;
    int xk = (tid & 7) * 8;
    bool gvalid = (m0 + gslot_i) < cnt;
    size_t grow = ((size_t)e * T_ + m0 + gslot_i) * I_;
    int wr = tid >> 2;
    int wq = tid & 3;
    long wrow = ((long)e * H_ + h0 + wr) * (I_ / 2);
    long srow = ((long)e * H_ + h0 + wr) * (I_ / GS);

    for (int kc = 0; kc < I_ / 64; kc++) {
        uint4 gv = make_uint4(0u, 0u, 0u, 0u);
        if (gvalid) gv = *(const uint4*)((const __nv_bfloat16*)g_gbuf + grow + kc * 64 + xk);
        const __nv_bfloat16* gb = (const __nv_bfloat16*)&gv;
#pragma unroll
        for (int j = 0; j < 8; j++) Gs[xk + j][gslot_i] = __bfloat162float(gb[j]);

        {
            long base = wrow + kc * 32 + wq * 8;
            int4 p0 = *(const int4*)(w2 + base);
            int4 p1 = *(const int4*)(w2 + base + 4);
            int s = w2s[srow + kc * 2 + (wq >> 1)];
            int vals[8] = {p0.x, p0.y, p0.z, p0.w, p1.x, p1.y, p1.z, p1.w};
#pragma unroll
            for (int m2 = 0; m2 < 8; m2++) {
                int v = vals[m2];
                Ws[wq * 16 + 2 * m2 + 0][wr] = dq(v & 15, s);
                Ws[wq * 16 + 2 * m2 + 1][wr] = dq((v >> 4) & 15, s);
            }
        }
        __syncthreads();

#pragma unroll 16
        for (int k = 0; k < 64; k++) {
            float2 a = *(const float2*)&Gs[k][ty * 2];
            float4 b = *(const float4*)&Ws[k][tx * 4];
            acc[0][0] += a.x * b.x; acc[0][1] += a.x * b.y;
            acc[0][2] += a.x * b.z; acc[0][3] += a.x * b.w;
            acc[1][0] += a.y * b.x; acc[1][1] += a.y * b.y;
            acc[1][2] += a.y * b.z; acc[1][3] += a.y * b.w;
        }
        __syncthreads();
    }

    int bf32 = g_b2f32;
    const float* bpf = (const float*)g_w2b + (long)e * H_;
    const __nv_bfloat16* bph = (const __nv_bfloat16*)g_w2b + (long)e * H_;
#pragma unroll
    for (int jt = 0; jt < 2; jt++) {
        int slot = m0 + ty * 2 + jt;
        if (slot >= cnt) continue;
        int entry = sent[ty * 2 + jt];
        int t = entry >> 1, kk = entry & 1;
        size_t obase = ((size_t)(t * 2 + kk)) * H_;
#pragma unroll
        for (int ji = 0; ji < 4; ji++) {
            int h = h0 + tx * 4 + ji;
            float bv = bf32 ? bpf[h] : __bfloat162float(bph[h]);
            float o = rb(acc[jt][ji]);   // einsum output -> bf16
            o = rb(o + bv);              // + bias -> bf16 (out_e materialized bf16)
            g_oslot[obase + h] = o;
        }
    }
}

// ---------------- K4: weighted combine ----------------
__global__ void __launch_bounds__(256) k_comb(void* __restrict__ out) {
    int idx = blockIdx.x * 256 + threadIdx.x;
    if (idx >= T_ * H_) return;
    int t = idx / H_;
    int h = idx - t * H_;
    float r = g_wts[t * 2 + 0] * g_oslot[(size_t)(t * 2 + 0) * H_ + h]
            + g_wts[t * 2 + 1] * g_oslot[(size_t)(t * 2 + 1) * H_ + h];
    __nv_bfloat16 v = __float2bfloat16(r);   // final astype(bf16)
    if (g_xf32) ((float*)out)[idx] = __bfloat162float(v);
    else        ((__nv_bfloat16*)out)[idx] = v;
}

// ---------------- host ----------------
extern "C" void kernel_launch(void* const* d_in, const int* in_sizes, int n_in,
                              void* d_out, int out_size) {
    const void *p2m0 = 0, *p2m1 = 0, *p16k0 = 0, *p16k1 = 0;
    const int *w1 = 0, *w3 = 0, *w2 = 0, *w13s = 0;
    const void *w13b = 0;

    int big_idx[3] = {-1, -1, -1};
    int nbig = 0, n2m = 0, n16k = 0;
    for (int i = 0; i < n_in; i++) {
        int s = in_sizes[i];
        if (s == 2097152) {
            if (n2m == 0) p2m0 = d_in[i]; else p2m1 = d_in[i];
            n2m++;
        } else if (s == 16384) {
            if (n16k == 0) p16k0 = d_in[i]; else p16k1 = d_in[i];
            n16k++;
        } else if (s == 4194304) {
            w13s = (const int*)d_in[i];
        } else if (s == 65536) {
            w13b = d_in[i];
        } else if (s == 33554432) {
            if (nbig < 3) big_idx[nbig] = i;
            nbig++;
        }
    }
    bool contiguous = (nbig == 3 && big_idx[1] == big_idx[0] + 1 &&
                       big_idx[2] == big_idx[1] + 1);
    w1 = (const int*)d_in[big_idx[0]];
    if (contiguous) {           // dict order: w1, w3, w2
        w3 = (const int*)d_in[big_idx[1]];
        w2 = (const int*)d_in[big_idx[2]];
    } else {                    // alphabetical: w1, w2, w3
        w2 = (const int*)d_in[big_idx[1]];
        w3 = (const int*)d_in[big_idx[2]];
    }

    k_probe<<<1, 32>>>(p2m0, p2m1, p16k0, p16k1, w13b);
    k_gate<<<T_ / 8, 256>>>();
    k_up<<<dim3(I_ / 64, T_ / 32, E_), 256>>>(w1, w3, w13s, w13b);
    k_down<<<dim3(H_ / 64, T_ / 32, E_), 256>>>(w2);
    k_comb<<<(T_ * H_ + 255) / 256, 256>>>(d_out);
}

// round 14
// speedup vs baseline: 2.5409x; 2.5409x over previous
#include <cuda_runtime.h>
#include <cuda_bf16.h>

#define T_  1024
#define H_  2048
#define I_  4096
#define E_  8
#define GS  32

// ---------------- static device scratch ----------------
__device__ __nv_bfloat16 g_gbuf[(size_t)E_ * T_ * I_];
__device__ float g_oslot[(size_t)T_ * 2 * H_];
__device__ float g_wts[T_ * 2];
__device__ int   g_cnt[E_];
__device__ int   g_entries[E_ * T_];

__device__ const void* g_x;
__device__ const int*  g_w2s;
__device__ const float* g_gw;
__device__ const void* g_w2b;
__device__ int g_xf32, g_b13f32, g_b2f32;

// fp4 e2m1 values as bf16 bit patterns
__constant__ unsigned short c_fp4h[16] = {
    0x0000, 0x3F00, 0x3F80, 0x3FC0, 0x4000, 0x4040, 0x4080, 0x40C0,
    0x8000, 0xBF00, 0xBF80, 0xBFC0, 0xC000, 0xC040, 0xC080, 0xC0C0};

__device__ int looks_f32(const unsigned* u, int n) {
    int small = 0;
    for (int i = 0; i < n; i++) {
        unsigned e = (u[i] >> 7) & 0xFF;
        if (e < 64) small++;
    }
    return small > (n >> 4);
}

__device__ __forceinline__ float rb(float v) {
    return __bfloat162float(__float2bfloat16(v));
}

__device__ __forceinline__ void mma16816(float* d, unsigned a0, unsigned a1,
                                         unsigned a2, unsigned a3,
                                         unsigned b0, unsigned b1) {
    asm volatile(
        "mma.sync.aligned.m16n8k16.row.col.f32.bf16.bf16.f32 "
        "{%0,%1,%2,%3},{%4,%5,%6,%7},{%8,%9},{%0,%1,%2,%3};"
        : "+f"(d[0]), "+f"(d[1]), "+f"(d[2]), "+f"(d[3])
        : "r"(a0), "r"(a1), "r"(a2), "r"(a3), "r"(b0), "r"(b1));
}

#define RS 20   // words per 32-bf16 SMEM row (16 data + 4 pad)

// ---------------- K-1: probe ----------------
__global__ void k_probe(const void* a2m0, const void* a2m1,
                        const void* a16k0, const void* a16k1,
                        const void* w13b) {
    if (threadIdx.x != 0) return;
    const unsigned* u = (const unsigned*)a2m0;
    bool allsmall = true;
    for (int i = 0; i < 4096; i++) if (u[i] >= 128u) { allsmall = false; break; }
    const void* xptr; const void* w2sptr;
    if (allsmall) { w2sptr = a2m0; xptr = a2m1; }
    else          { xptr = a2m0;  w2sptr = a2m1; }
    g_x = xptr; g_w2s = (const int*)w2sptr;
    const float* f = (const float*)a16k0;
    bool big = false;
    for (int i = 0; i < 4096; i++) if (fabsf(f[i]) >= 1.f) { big = true; break; }
    const void* gwp; const void* w2bp;
    if (big) { w2bp = a16k0; gwp = a16k1; }
    else     { gwp = a16k0;  w2bp = a16k1; }
    g_gw = (const float*)gwp; g_w2b = w2bp;
    g_xf32   = looks_f32((const unsigned*)xptr, 256);
    g_b13f32 = looks_f32((const unsigned*)w13b, 256);
    g_b2f32  = looks_f32((const unsigned*)w2bp, 256);
    for (int e = 0; e < E_; e++) g_cnt[e] = 0;
}

// ---------------- K1: gating ----------------
__global__ void __launch_bounds__(256) k_gate() {
    const float* gw = g_gw;
    int xf = g_xf32;
    const float* xf32 = (const float*)g_x;
    const __nv_bfloat16* xb = (const __nv_bfloat16*)g_x;
    int warp = threadIdx.x >> 5, lane = threadIdx.x & 31;
    int t = blockIdx.x * 8 + warp;
    float acc[E_];
#pragma unroll
    for (int e = 0; e < E_; e++) acc[e] = 0.f;
    for (int h = lane; h < H_; h += 32) {
        float xv = xf ? xf32[(size_t)t * H_ + h]
                      : __bfloat162float(xb[(size_t)t * H_ + h]);
#pragma unroll
        for (int e = 0; e < E_; e++) acc[e] += xv * gw[e * H_ + h];
    }
#pragma unroll
    for (int e = 0; e < E_; e++) {
#pragma unroll
        for (int off = 16; off > 0; off >>= 1)
            acc[e] += __shfl_xor_sync(0xffffffffu, acc[e], off);
    }
    if (lane == 0) {
        float m = acc[0];
#pragma unroll
        for (int e = 1; e < E_; e++) m = fmaxf(m, acc[e]);
        float p[E_], s = 0.f;
#pragma unroll
        for (int e = 0; e < E_; e++) { p[e] = expf(acc[e] - m); s += p[e]; }
#pragma unroll
        for (int e = 0; e < E_; e++) p[e] /= s;
        int i0 = 0; float p0v = p[0];
#pragma unroll
        for (int e = 1; e < E_; e++) if (p[e] > p0v) { p0v = p[e]; i0 = e; }
        int i1 = -1; float p1v = -1.f;
#pragma unroll
        for (int e = 0; e < E_; e++) {
            if (e == i0) continue;
            if (p[e] > p1v) { p1v = p[e]; i1 = e; }
        }
        float ws = p0v + p1v;
        g_wts[t * 2 + 0] = p0v / ws;
        g_wts[t * 2 + 1] = p1v / ws;
        int pos = atomicAdd(&g_cnt[i0], 1);
        g_entries[i0 * T_ + pos] = (t << 1);
        pos = atomicAdd(&g_cnt[i1], 1);
        g_entries[i1 * T_ + pos] = (t << 1) | 1;
    }
}

// ---------------- K2: routed up projection (HMMA) ----------------
// Tile: 128 I-rows x 32 slots, K-chunk 32. 8 warps = 4 m-warps x 2 n-warps.
// NOTE: each int32 of w1/w3 holds ONE byte = two fp4 nibbles.
__global__ void __launch_bounds__(256) k_up(const int* __restrict__ w1,
                                            const int* __restrict__ w3,
                                            const int* __restrict__ w13s,
                                            const void* __restrict__ w13b) {
    int e = blockIdx.z;
    int cnt = g_cnt[e];
    int m0 = blockIdx.y * 32;
    if (m0 >= cnt) return;
    int i0 = blockIdx.x * 128;

    __shared__ unsigned W1s[128 * RS];
    __shared__ unsigned W3s[128 * RS];
    __shared__ unsigned Xs[32 * RS];
    __shared__ unsigned LUT[256];
    __shared__ int stok[32];

    int tid = threadIdx.x;
    {
        unsigned lo = c_fp4h[tid & 15], hi = c_fp4h[(tid >> 4) & 15];
        LUT[tid] = lo | (hi << 16);
    }
    if (tid < 32) {
        int slot = m0 + tid;
        stok[tid] = (slot < cnt) ? (g_entries[e * T_ + slot] >> 1) : -1;
    }
    __syncthreads();

    int xf = g_xf32;
    int lane = tid & 31, wid = tid >> 5;
    int wm = wid & 3, wn = wid >> 2;          // warp tile coords
    int gq = lane >> 2, cq = lane & 3;        // fragment coords

    // loader roles
    int xslot = tid >> 3, xseg = tid & 7;     // X: 32 slots x 8 segs of 4 elems
    int xt = stok[xslot];
    int wr = tid >> 1, wh = tid & 1;          // W: 128 rows x 2 halves (8 int32 each)
    // one int32 = 2 fp4 values; row stride = H_/2 int32; per 32-k chunk = 16 int32
    const int4* w1p = (const int4*)(w1 + ((long)e * I_ + i0 + wr) * (H_ / 2)) + wh * 2;
    const int4* w3p = (const int4*)(w3 + ((long)e * I_ + i0 + wr) * (H_ / 2)) + wh * 2;
    long s1row = ((long)e * 2 * I_ + i0 + wr) * (H_ / GS);
    long s3row = ((long)e * 2 * I_ + I_ + i0 + wr) * (H_ / GS);

    float acc[2][2][2][4];                    // [mat][mtile][ntile][frag]
#pragma unroll
    for (int a = 0; a < 2; a++)
#pragma unroll
        for (int b = 0; b < 2; b++)
#pragma unroll
            for (int c = 0; c < 2; c++)
#pragma unroll
                for (int d = 0; d < 4; d++) acc[a][b][c][d] = 0.f;

    for (int kc = 0; kc < H_ / 32; kc++) {
        __syncthreads();
        // ---- X tile ----
        {
            unsigned lo = 0, hi = 0;
            if (xt >= 0) {
                if (xf) {
                    float4 v = *(const float4*)((const float*)g_x +
                               (size_t)xt * H_ + kc * 32 + xseg * 4);
                    __nv_bfloat162 p0 = __floats2bfloat162_rn(v.x, v.y);
                    __nv_bfloat162 p1 = __floats2bfloat162_rn(v.z, v.w);
                    lo = *(unsigned*)&p0; hi = *(unsigned*)&p1;
                } else {
                    uint2 v = *(const uint2*)((const __nv_bfloat16*)g_x +
                              (size_t)xt * H_ + kc * 32 + xseg * 4);
                    lo = v.x; hi = v.y;
                }
            }
            Xs[xslot * RS + xseg * 2 + 0] = lo;
            Xs[xslot * RS + xseg * 2 + 1] = hi;
        }
        // ---- W1 / W3 dequant (2 threads per row; 8 int32 -> 8 bf16x2 words each) ----
        {
            int s1 = w13s[s1row + kc];
            unsigned sb = (unsigned)(s1 << 7) * 0x10001u;
            __nv_bfloat162 sc = *(__nv_bfloat162*)&sb;
            int4 p0 = w1p[kc * 4];
            int4 p1 = w1p[kc * 4 + 1];
            unsigned vv[8] = {(unsigned)p0.x, (unsigned)p0.y, (unsigned)p0.z,
                              (unsigned)p0.w, (unsigned)p1.x, (unsigned)p1.y,
                              (unsigned)p1.z, (unsigned)p1.w};
#pragma unroll
            for (int j = 0; j < 8; j++) {
                unsigned lw = LUT[vv[j] & 255];
                __nv_bfloat162 r = __hmul2(*(__nv_bfloat162*)&lw, sc);
                W1s[wr * RS + wh * 8 + j] = *(unsigned*)&r;
            }
            int s3 = w13s[s3row + kc];
            unsigned sb3 = (unsigned)(s3 << 7) * 0x10001u;
            __nv_bfloat162 sc3 = *(__nv_bfloat162*)&sb3;
            int4 q0 = w3p[kc * 4];
            int4 q1 = w3p[kc * 4 + 1];
            unsigned qq[8] = {(unsigned)q0.x, (unsigned)q0.y, (unsigned)q0.z,
                              (unsigned)q0.w, (unsigned)q1.x, (unsigned)q1.y,
                              (unsigned)q1.z, (unsigned)q1.w};
#pragma unroll
            for (int j = 0; j < 8; j++) {
                unsigned lw = LUT[qq[j] & 255];
                __nv_bfloat162 r = __hmul2(*(__nv_bfloat162*)&lw, sc3);
                W3s[wr * RS + wh * 8 + j] = *(unsigned*)&r;
            }
        }
        __syncthreads();
        // ---- MMA ----
#pragma unroll
        for (int kst = 0; kst < 2; kst++) {
            unsigned bf[2][2];
#pragma unroll
            for (int nt = 0; nt < 2; nt++) {
                int bidx = (wn * 16 + nt * 8 + gq) * RS + kst * 8 + cq;
                bf[nt][0] = Xs[bidx];
                bf[nt][1] = Xs[bidx + 4];
            }
#pragma unroll
            for (int mt = 0; mt < 2; mt++) {
                int aidx = (wm * 32 + mt * 16 + gq) * RS + kst * 8 + cq;
                unsigned a0 = W1s[aidx], a1 = W1s[aidx + 8 * RS];
                unsigned a2 = W1s[aidx + 4], a3 = W1s[aidx + 8 * RS + 4];
#pragma unroll
                for (int nt = 0; nt < 2; nt++)
                    mma16816(acc[0][mt][nt], a0, a1, a2, a3, bf[nt][0], bf[nt][1]);
                unsigned c0 = W3s[aidx], c1 = W3s[aidx + 8 * RS];
                unsigned c2 = W3s[aidx + 4], c3 = W3s[aidx + 8 * RS + 4];
#pragma unroll
                for (int nt = 0; nt < 2; nt++)
                    mma16816(acc[1][mt][nt], c0, c1, c2, c3, bf[nt][0], bf[nt][1]);
            }
        }
    }

    // ---- epilogue (frozen numerics chain) ----
    int bf32 = g_b13f32;
    const float* bpf = (const float*)w13b + (long)e * 2 * I_;
    const __nv_bfloat16* bph = (const __nv_bfloat16*)w13b + (long)e * 2 * I_;
#pragma unroll
    for (int mt = 0; mt < 2; mt++) {
#pragma unroll
        for (int rr = 0; rr < 2; rr++) {
            int i = i0 + wm * 32 + mt * 16 + gq + rr * 8;
            float b1v = bf32 ? bpf[i]      : __bfloat162float(bph[i]);
            float b3v = bf32 ? bpf[I_ + i] : __bfloat162float(bph[I_ + i]);
#pragma unroll
            for (int nt = 0; nt < 2; nt++) {
#pragma unroll
                for (int cc = 0; cc < 2; cc++) {
                    int slot = m0 + wn * 16 + nt * 8 + 2 * cq + cc;
                    if (slot >= cnt) continue;
                    float a1v = acc[0][mt][nt][rr * 2 + cc];
                    float a3v = acc[1][mt][nt][rr * 2 + cc];
                    float h1 = rb(a1v);
                    h1 = rb(h1 + b1v);
                    float h3 = rb(a3v);
                    h3 = rb(h3 + b3v);
                    float em  = rb(expf(-h1));
                    float den = rb(1.f + em);
                    float sg  = rb(1.f / den);
                    float sl  = rb(h1 * sg);
                    g_gbuf[((size_t)e * T_ + slot) * I_ + i] =
                        __float2bfloat16(sl * h3);
                }
            }
        }
    }
}

// ---------------- K3: routed down projection (HMMA) ----------------
__global__ void __launch_bounds__(256) k_down(const int* __restrict__ w2) {
    const int* w2s = g_w2s;
    int e = blockIdx.z;
    int cnt = g_cnt[e];
    int m0 = blockIdx.y * 32;
    if (m0 >= cnt) return;
    int h0 = blockIdx.x * 128;

    __shared__ unsigned Ws[128 * RS];
    __shared__ unsigned Gs[32 * RS];
    __shared__ unsigned LUT[256];
    __shared__ int sent[32];

    int tid = threadIdx.x;
    {
        unsigned lo = c_fp4h[tid & 15], hi = c_fp4h[(tid >> 4) & 15];
        LUT[tid] = lo | (hi << 16);
    }
    if (tid < 32) {
        int slot = m0 + tid;
        sent[tid] = (slot < cnt) ? g_entries[e * T_ + slot] : -1;
    }
    __syncthreads();

    int lane = tid & 31, wid = tid >> 5;
    int wm = wid & 3, wn = wid >> 2;
    int gq = lane >> 2, cq = lane & 3;

    int gslot = tid >> 3, gseg = tid & 7;
    size_t grow = ((size_t)e * T_ + m0 + gslot) * I_;
    int wr = tid >> 1, wh = tid & 1;
    const int4* w2p = (const int4*)(w2 + ((long)e * H_ + h0 + wr) * (I_ / 2)) + wh * 2;
    long srow = ((long)e * H_ + h0 + wr) * (I_ / GS);

    float acc[2][2][4];
#pragma unroll
    for (int a = 0; a < 2; a++)
#pragma unroll
        for (int b = 0; b < 2; b++)
#pragma unroll
            for (int d = 0; d < 4; d++) acc[a][b][d] = 0.f;

    for (int kc = 0; kc < I_ / 32; kc++) {
        __syncthreads();
        {
            uint2 v = *(const uint2*)((const __nv_bfloat16*)g_gbuf + grow +
                                      kc * 32 + gseg * 4);
            Gs[gslot * RS + gseg * 2 + 0] = v.x;
            Gs[gslot * RS + gseg * 2 + 1] = v.y;
        }
        {
            int s = w2s[srow + kc];
            unsigned sb = (unsigned)(s << 7) * 0x10001u;
            __nv_bfloat162 sc = *(__nv_bfloat162*)&sb;
            int4 p0 = w2p[kc * 4];
            int4 p1 = w2p[kc * 4 + 1];
            unsigned vv[8] = {(unsigned)p0.x, (unsigned)p0.y, (unsigned)p0.z,
                              (unsigned)p0.w, (unsigned)p1.x, (unsigned)p1.y,
                              (unsigned)p1.z, (unsigned)p1.w};
#pragma unroll
            for (int j = 0; j < 8; j++) {
                unsigned lw = LUT[vv[j] & 255];
                __nv_bfloat162 r = __hmul2(*(__nv_bfloat162*)&lw, sc);
                Ws[wr * RS + wh * 8 + j] = *(unsigned*)&r;
            }
        }
        __syncthreads();
#pragma unroll
        for (int kst = 0; kst < 2; kst++) {
            unsigned bf[2][2];
#pragma unroll
            for (int nt = 0; nt < 2; nt++) {
                int bidx = (wn * 16 + nt * 8 + gq) * RS + kst * 8 + cq;
                bf[nt][0] = Gs[bidx];
                bf[nt][1] = Gs[bidx + 4];
            }
#pragma unroll
            for (int mt = 0; mt < 2; mt++) {
                int aidx = (wm * 32 + mt * 16 + gq) * RS + kst * 8 + cq;
                unsigned a0 = Ws[aidx], a1 = Ws[aidx + 8 * RS];
                unsigned a2 = Ws[aidx + 4], a3 = Ws[aidx + 8 * RS + 4];
#pragma unroll
                for (int nt = 0; nt < 2; nt++)
                    mma16816(acc[mt][nt], a0, a1, a2, a3, bf[nt][0], bf[nt][1]);
            }
        }
    }

    int bf32 = g_b2f32;
    const float* bpf = (const float*)g_w2b + (long)e * H_;
    const __nv_bfloat16* bph = (const __nv_bfloat16*)g_w2b + (long)e * H_;
#pragma unroll
    for (int mt = 0; mt < 2; mt++) {
#pragma unroll
        for (int rr = 0; rr < 2; rr++) {
            int h = h0 + wm * 32 + mt * 16 + gq + rr * 8;
            float bv = bf32 ? bpf[h] : __bfloat162float(bph[h]);
#pragma unroll
            for (int nt = 0; nt < 2; nt++) {
#pragma unroll
                for (int cc = 0; cc < 2; cc++) {
                    int sl = m0 + wn * 16 + nt * 8 + 2 * cq + cc;
                    if (sl >= cnt) continue;
                    int entry = sent[sl - m0];
                    int t = entry >> 1, kk = entry & 1;
                    float o = rb(acc[mt][nt][rr * 2 + cc]);
                    o = rb(o + bv);
                    g_oslot[((size_t)(t * 2 + kk)) * H_ + h] = o;
                }
            }
        }
    }
}

// ---------------- K4: weighted combine ----------------
__global__ void __launch_bounds__(256) k_comb(void* __restrict__ out) {
    int idx = blockIdx.x * 256 + threadIdx.x;
    if (idx >= T_ * H_) return;
    int t = idx / H_;
    int h = idx - t * H_;
    float r = g_wts[t * 2 + 0] * g_oslot[(size_t)(t * 2 + 0) * H_ + h]
            + g_wts[t * 2 + 1] * g_oslot[(size_t)(t * 2 + 1) * H_ + h];
    __nv_bfloat16 v = __float2bfloat16(r);
    if (g_xf32) ((float*)out)[idx] = __bfloat162float(v);
    else        ((__nv_bfloat16*)out)[idx] = v;
}

// ---------------- host ----------------
extern "C" void kernel_launch(void* const* d_in, const int* in_sizes, int n_in,
                              void* d_out, int out_size) {
    const void *p2m0 = 0, *p2m1 = 0, *p16k0 = 0, *p16k1 = 0;
    const int *w1 = 0, *w3 = 0, *w2 = 0, *w13s = 0;
    const void *w13b = 0;

    int big_idx[3] = {-1, -1, -1};
    int nbig = 0, n2m = 0, n16k = 0;
    for (int i = 0; i < n_in; i++) {
        int s = in_sizes[i];
        if (s == 2097152) {
            if (n2m == 0) p2m0 = d_in[i]; else p2m1 = d_in[i];
            n2m++;
        } else if (s == 16384) {
            if (n16k == 0) p16k0 = d_in[i]; else p16k1 = d_in[i];
            n16k++;
        } else if (s == 4194304) {
            w13s = (const int*)d_in[i];
        } else if (s == 65536) {
            w13b = d_in[i];
        } else if (s == 33554432) {
            if (nbig < 3) big_idx[nbig] = i;
            nbig++;
        }
    }
    bool contiguous = (nbig == 3 && big_idx[1] == big_idx[0] + 1 &&
                       big_idx[2] == big_idx[1] + 1);
    w1 = (const int*)d_in[big_idx[0]];
    if (contiguous) {           // dict order: w1, w3, w2
        w3 = (const int*)d_in[big_idx[1]];
        w2 = (const int*)d_in[big_idx[2]];
    } else {                    // alphabetical: w1, w2, w3
        w2 = (const int*)d_in[big_idx[1]];
        w3 = (const int*)d_in[big_idx[2]];
    }

    k_probe<<<1, 256>>>(p2m0, p2m1, p16k0, p16k1, w13b);
    k_gate<<<T_ / 8, 256>>>();
    k_up<<<dim3(I_ / 128, T_ / 32, E_), 256>>>(w1, w3, w13s, w13b);
    k_down<<<dim3(H_ / 128, T_ / 32, E_), 256>>>(w2);
    k_comb<<<(T_ * H_ + 255) / 256, 256>>>(d_out);
}

// round 15
// speedup vs baseline: 3.5345x; 1.3910x over previous
#include <cuda_runtime.h>
#include <cuda_bf16.h>

#define T_  1024
#define H_  2048
#define I_  4096
#define E_  8
#define GS  32
#define RS  20   // words per 32-bf16 SMEM row (16 data + 4 pad), 16B-aligned rows

// ---------------- static device scratch ----------------
__device__ __nv_bfloat16 g_gbuf[(size_t)E_ * T_ * I_];
__device__ float g_oslot[(size_t)T_ * 2 * H_];
__device__ float g_wts[T_ * 2];
__device__ int   g_cnt[E_];
__device__ int   g_entries[E_ * T_];

__device__ const void* g_x;
__device__ const int*  g_w2s;
__device__ const float* g_gw;
__device__ const void* g_w2b;
__device__ int g_xf32, g_b13f32, g_b2f32;

__constant__ unsigned short c_fp4h[16] = {
    0x0000, 0x3F00, 0x3F80, 0x3FC0, 0x4000, 0x4040, 0x4080, 0x40C0,
    0x8000, 0xBF00, 0xBF80, 0xBFC0, 0xC000, 0xC040, 0xC080, 0xC0C0};

__device__ int looks_f32(const unsigned* u, int n) {
    int small = 0;
    for (int i = 0; i < n; i++) {
        unsigned e = (u[i] >> 7) & 0xFF;
        if (e < 64) small++;
    }
    return small > (n >> 4);
}

__device__ __forceinline__ float rb(float v) {
    return __bfloat162float(__float2bfloat16(v));
}

__device__ __forceinline__ void mma16816(float* d, unsigned a0, unsigned a1,
                                         unsigned a2, unsigned a3,
                                         unsigned b0, unsigned b1) {
    asm volatile(
        "mma.sync.aligned.m16n8k16.row.col.f32.bf16.bf16.f32 "
        "{%0,%1,%2,%3},{%4,%5,%6,%7},{%8,%9},{%0,%1,%2,%3};"
        : "+f"(d[0]), "+f"(d[1]), "+f"(d[2]), "+f"(d[3])
        : "r"(a0), "r"(a1), "r"(a2), "r"(a3), "r"(b0), "r"(b1));
}

__device__ __forceinline__ void ldsm4(unsigned& r0, unsigned& r1,
                                      unsigned& r2, unsigned& r3,
                                      const unsigned* p) {
    unsigned addr = (unsigned)__cvta_generic_to_shared(p);
    asm volatile("ldmatrix.sync.aligned.m8n8.x4.shared.b16 {%0,%1,%2,%3},[%4];"
                 : "=r"(r0), "=r"(r1), "=r"(r2), "=r"(r3) : "r"(addr));
}

// ---------------- K-1: probe ----------------
__global__ void k_probe(const void* a2m0, const void* a2m1,
                        const void* a16k0, const void* a16k1,
                        const void* w13b) {
    if (threadIdx.x != 0) return;
    const unsigned* u = (const unsigned*)a2m0;
    bool allsmall = true;
    for (int i = 0; i < 4096; i++) if (u[i] >= 128u) { allsmall = false; break; }
    const void* xptr; const void* w2sptr;
    if (allsmall) { w2sptr = a2m0; xptr = a2m1; }
    else          { xptr = a2m0;  w2sptr = a2m1; }
    g_x = xptr; g_w2s = (const int*)w2sptr;
    const float* f = (const float*)a16k0;
    bool big = false;
    for (int i = 0; i < 4096; i++) if (fabsf(f[i]) >= 1.f) { big = true; break; }
    const void* gwp; const void* w2bp;
    if (big) { w2bp = a16k0; gwp = a16k1; }
    else     { gwp = a16k0;  w2bp = a16k1; }
    g_gw = (const float*)gwp; g_w2b = w2bp;
    g_xf32   = looks_f32((const unsigned*)xptr, 256);
    g_b13f32 = looks_f32((const unsigned*)w13b, 256);
    g_b2f32  = looks_f32((const unsigned*)w2bp, 256);
    for (int e = 0; e < E_; e++) g_cnt[e] = 0;
}

// ---------------- K1: gating ----------------
__global__ void __launch_bounds__(256) k_gate() {
    const float* gw = g_gw;
    int xf = g_xf32;
    const float* xf32 = (const float*)g_x;
    const __nv_bfloat16* xb = (const __nv_bfloat16*)g_x;
    int warp = threadIdx.x >> 5, lane = threadIdx.x & 31;
    int t = blockIdx.x * 8 + warp;
    float acc[E_];
#pragma unroll
    for (int e = 0; e < E_; e++) acc[e] = 0.f;
    for (int h = lane; h < H_; h += 32) {
        float xv = xf ? xf32[(size_t)t * H_ + h]
                      : __bfloat162float(xb[(size_t)t * H_ + h]);
#pragma unroll
        for (int e = 0; e < E_; e++) acc[e] += xv * gw[e * H_ + h];
    }
#pragma unroll
    for (int e = 0; e < E_; e++) {
#pragma unroll
        for (int off = 16; off > 0; off >>= 1)
            acc[e] += __shfl_xor_sync(0xffffffffu, acc[e], off);
    }
    if (lane == 0) {
        float m = acc[0];
#pragma unroll
        for (int e = 1; e < E_; e++) m = fmaxf(m, acc[e]);
        float p[E_], s = 0.f;
#pragma unroll
        for (int e = 0; e < E_; e++) { p[e] = expf(acc[e] - m); s += p[e]; }
#pragma unroll
        for (int e = 0; e < E_; e++) p[e] /= s;
        int i0 = 0; float p0v = p[0];
#pragma unroll
        for (int e = 1; e < E_; e++) if (p[e] > p0v) { p0v = p[e]; i0 = e; }
        int i1 = -1; float p1v = -1.f;
#pragma unroll
        for (int e = 0; e < E_; e++) {
            if (e == i0) continue;
            if (p[e] > p1v) { p1v = p[e]; i1 = e; }
        }
        float ws = p0v + p1v;
        g_wts[t * 2 + 0] = p0v / ws;
        g_wts[t * 2 + 1] = p1v / ws;
        int pos = atomicAdd(&g_cnt[i0], 1);
        g_entries[i0 * T_ + pos] = (t << 1);
        pos = atomicAdd(&g_cnt[i1], 1);
        g_entries[i1 * T_ + pos] = (t << 1) | 1;
    }
}

// ---------------- K2: up projection (HMMA + ldmatrix), 128 I-rows x 64 slots ----------------
__global__ void __launch_bounds__(256) k_up(const int* __restrict__ w1,
                                            const int* __restrict__ w3,
                                            const int* __restrict__ w13s,
                                            const void* __restrict__ w13b) {
    int e = blockIdx.z;
    int cnt = g_cnt[e];
    int bn0 = blockIdx.y * 64;
    if (bn0 >= cnt) return;
    int i0 = blockIdx.x * 128;

    __shared__ __align__(16) unsigned W1s[128 * RS];
    __shared__ __align__(16) unsigned W3s[128 * RS];
    __shared__ __align__(16) unsigned Xs[64 * RS];
    __shared__ unsigned LUT[256];
    __shared__ int stok[64];

    int tid = threadIdx.x;
    {
        unsigned lo = c_fp4h[tid & 15], hi = c_fp4h[(tid >> 4) & 15];
        LUT[tid] = lo | (hi << 16);
    }
    if (tid < 64) {
        int slot = bn0 + tid;
        stok[tid] = (slot < cnt) ? (g_entries[e * T_ + slot] >> 1) : -1;
    }
    __syncthreads();

    int xf = g_xf32;
    int lane = tid & 31, wid = tid >> 5;
    int wm = wid & 3, wn = wid >> 2;
    int gq = lane >> 2, cq = lane & 3;
    int lrow = (lane & 7) + ((lane >> 3) & 1) * 8;
    int lword = ((lane >> 4) & 1) * 4;

    // staging roles
    int xslot = tid >> 2, xseg = tid & 3;        // X: 64 slots x 4 segs (8 bf16)
    int xt = stok[xslot];
    int wr = tid & 127, wh = tid >> 7;           // W: 128 rows x 2 halves (8 int32)
    const int* w1row = w1 + ((long)e * I_ + i0 + wr) * (H_ / 2) + wh * 8;
    const int* w3row = w3 + ((long)e * I_ + i0 + wr) * (H_ / 2) + wh * 8;
    long s1row = ((long)e * 2 * I_ + i0 + wr) * (H_ / GS);
    long s3row = ((long)e * 2 * I_ + I_ + i0 + wr) * (H_ / GS);

    float acc[2][2][4][4];     // [mat][mt][nt][frag]
#pragma unroll
    for (int a = 0; a < 2; a++)
#pragma unroll
        for (int b = 0; b < 2; b++)
#pragma unroll
            for (int c = 0; c < 4; c++)
#pragma unroll
                for (int d = 0; d < 4; d++) acc[a][b][c][d] = 0.f;

    for (int kc = 0; kc < H_ / 32; kc++) {
        __syncthreads();
        // ---- X stage ----
        {
            uint4 ov = make_uint4(0u, 0u, 0u, 0u);
            if (xt >= 0) {
                if (xf) {
                    const float* xp = (const float*)g_x + (size_t)xt * H_ +
                                      kc * 32 + xseg * 8;
                    float4 v0 = ((const float4*)xp)[0];
                    float4 v1 = ((const float4*)xp)[1];
                    __nv_bfloat162 p0 = __floats2bfloat162_rn(v0.x, v0.y);
                    __nv_bfloat162 p1 = __floats2bfloat162_rn(v0.z, v0.w);
                    __nv_bfloat162 p2 = __floats2bfloat162_rn(v1.x, v1.y);
                    __nv_bfloat162 p3 = __floats2bfloat162_rn(v1.z, v1.w);
                    ov.x = *(unsigned*)&p0; ov.y = *(unsigned*)&p1;
                    ov.z = *(unsigned*)&p2; ov.w = *(unsigned*)&p3;
                } else {
                    ov = *(const uint4*)((const __nv_bfloat16*)g_x +
                         (size_t)xt * H_ + kc * 32 + xseg * 8);
                }
            }
            *(uint4*)&Xs[xslot * RS + xseg * 4] = ov;
        }
        // ---- W1 / W3 stage (vectorized, LUT dequant) ----
        {
            int s1 = w13s[s1row + kc];
            unsigned sb = (unsigned)(s1 << 7) * 0x10001u;
            __nv_bfloat162 sc = *(__nv_bfloat162*)&sb;
            int4 v0 = *(const int4*)(w1row + kc * 16);
            int4 v1 = *(const int4*)(w1row + kc * 16 + 4);
            uint4 o0, o1;
            {
                __nv_bfloat162 r;
                unsigned lw;
                lw = LUT[v0.x & 255]; r = __hmul2(*(__nv_bfloat162*)&lw, sc); o0.x = *(unsigned*)&r;
                lw = LUT[v0.y & 255]; r = __hmul2(*(__nv_bfloat162*)&lw, sc); o0.y = *(unsigned*)&r;
                lw = LUT[v0.z & 255]; r = __hmul2(*(__nv_bfloat162*)&lw, sc); o0.z = *(unsigned*)&r;
                lw = LUT[v0.w & 255]; r = __hmul2(*(__nv_bfloat162*)&lw, sc); o0.w = *(unsigned*)&r;
                lw = LUT[v1.x & 255]; r = __hmul2(*(__nv_bfloat162*)&lw, sc); o1.x = *(unsigned*)&r;
                lw = LUT[v1.y & 255]; r = __hmul2(*(__nv_bfloat162*)&lw, sc); o1.y = *(unsigned*)&r;
                lw = LUT[v1.z & 255]; r = __hmul2(*(__nv_bfloat162*)&lw, sc); o1.z = *(unsigned*)&r;
                lw = LUT[v1.w & 255]; r = __hmul2(*(__nv_bfloat162*)&lw, sc); o1.w = *(unsigned*)&r;
            }
            *(uint4*)&W1s[wr * RS + wh * 8] = o0;
            *(uint4*)&W1s[wr * RS + wh * 8 + 4] = o1;

            int s3 = w13s[s3row + kc];
            unsigned sb3 = (unsigned)(s3 << 7) * 0x10001u;
            __nv_bfloat162 sc3 = *(__nv_bfloat162*)&sb3;
            int4 q0 = *(const int4*)(w3row + kc * 16);
            int4 q1 = *(const int4*)(w3row + kc * 16 + 4);
            uint4 t0, t1;
            {
                __nv_bfloat162 r;
                unsigned lw;
                lw = LUT[q0.x & 255]; r = __hmul2(*(__nv_bfloat162*)&lw, sc3); t0.x = *(unsigned*)&r;
                lw = LUT[q0.y & 255]; r = __hmul2(*(__nv_bfloat162*)&lw, sc3); t0.y = *(unsigned*)&r;
                lw = LUT[q0.z & 255]; r = __hmul2(*(__nv_bfloat162*)&lw, sc3); t0.z = *(unsigned*)&r;
                lw = LUT[q0.w & 255]; r = __hmul2(*(__nv_bfloat162*)&lw, sc3); t0.w = *(unsigned*)&r;
                lw = LUT[q1.x & 255]; r = __hmul2(*(__nv_bfloat162*)&lw, sc3); t1.x = *(unsigned*)&r;
                lw = LUT[q1.y & 255]; r = __hmul2(*(__nv_bfloat162*)&lw, sc3); t1.y = *(unsigned*)&r;
                lw = LUT[q1.z & 255]; r = __hmul2(*(__nv_bfloat162*)&lw, sc3); t1.z = *(unsigned*)&r;
                lw = LUT[q1.w & 255]; r = __hmul2(*(__nv_bfloat162*)&lw, sc3); t1.w = *(unsigned*)&r;
            }
            *(uint4*)&W3s[wr * RS + wh * 8] = t0;
            *(uint4*)&W3s[wr * RS + wh * 8 + 4] = t1;
        }
        __syncthreads();

        // ---- fragments + MMA ----
#pragma unroll
        for (int kst = 0; kst < 2; kst++) {
            unsigned b[2][4];
#pragma unroll
            for (int p = 0; p < 2; p++)
                ldsm4(b[p][0], b[p][1], b[p][2], b[p][3],
                      &Xs[(wn * 32 + p * 16 + lrow) * RS + kst * 8 + lword]);
#pragma unroll
            for (int mt = 0; mt < 2; mt++) {
                unsigned a0, a1, a2, a3;
                ldsm4(a0, a1, a2, a3,
                      &W1s[(wm * 32 + mt * 16 + lrow) * RS + kst * 8 + lword]);
#pragma unroll
                for (int nt = 0; nt < 4; nt++)
                    mma16816(acc[0][mt][nt], a0, a1, a2, a3,
                             b[nt >> 1][nt & 1], b[nt >> 1][2 + (nt & 1)]);
                unsigned c0, c1, c2, c3;
                ldsm4(c0, c1, c2, c3,
                      &W3s[(wm * 32 + mt * 16 + lrow) * RS + kst * 8 + lword]);
#pragma unroll
                for (int nt = 0; nt < 4; nt++)
                    mma16816(acc[1][mt][nt], c0, c1, c2, c3,
                             b[nt >> 1][nt & 1], b[nt >> 1][2 + (nt & 1)]);
            }
        }
    }

    // ---- epilogue (frozen numerics) ----
    int bf32 = g_b13f32;
    const float* bpf = (const float*)w13b + (long)e * 2 * I_;
    const __nv_bfloat16* bph = (const __nv_bfloat16*)w13b + (long)e * 2 * I_;
#pragma unroll
    for (int mt = 0; mt < 2; mt++) {
#pragma unroll
        for (int rr = 0; rr < 2; rr++) {
            int i = i0 + wm * 32 + mt * 16 + gq + rr * 8;
            float b1v = bf32 ? bpf[i]      : __bfloat162float(bph[i]);
            float b3v = bf32 ? bpf[I_ + i] : __bfloat162float(bph[I_ + i]);
#pragma unroll
            for (int nt = 0; nt < 4; nt++) {
#pragma unroll
                for (int cc = 0; cc < 2; cc++) {
                    int slot = bn0 + wn * 32 + nt * 8 + 2 * cq + cc;
                    if (slot >= cnt) continue;
                    float h1 = rb(acc[0][mt][nt][rr * 2 + cc]);
                    h1 = rb(h1 + b1v);
                    float h3 = rb(acc[1][mt][nt][rr * 2 + cc]);
                    h3 = rb(h3 + b3v);
                    float em  = rb(expf(-h1));
                    float den = rb(1.f + em);
                    float sg  = rb(1.f / den);
                    float sl  = rb(h1 * sg);
                    g_gbuf[((size_t)e * T_ + slot) * I_ + i] =
                        __float2bfloat16(sl * h3);
                }
            }
        }
    }
}

// ---------------- K3: down projection (HMMA + ldmatrix), 128 H-rows x 64 slots ----------------
__global__ void __launch_bounds__(256) k_down(const int* __restrict__ w2) {
    const int* w2s = g_w2s;
    int e = blockIdx.z;
    int cnt = g_cnt[e];
    int bn0 = blockIdx.y * 64;
    if (bn0 >= cnt) return;
    int h0 = blockIdx.x * 128;

    __shared__ __align__(16) unsigned Ws[128 * RS];
    __shared__ __align__(16) unsigned Gs[64 * RS];
    __shared__ unsigned LUT[256];
    __shared__ int sent[64];

    int tid = threadIdx.x;
    {
        unsigned lo = c_fp4h[tid & 15], hi = c_fp4h[(tid >> 4) & 15];
        LUT[tid] = lo | (hi << 16);
    }
    if (tid < 64) {
        int slot = bn0 + tid;
        sent[tid] = (slot < cnt) ? g_entries[e * T_ + slot] : -1;
    }
    __syncthreads();

    int lane = tid & 31, wid = tid >> 5;
    int wm = wid & 3, wn = wid >> 2;
    int gq = lane >> 2, cq = lane & 3;
    int lrow = (lane & 7) + ((lane >> 3) & 1) * 8;
    int lword = ((lane >> 4) & 1) * 4;

    int gslot = tid >> 2, gseg = tid & 3;
    size_t grow = ((size_t)e * T_ + bn0 + gslot) * I_;
    int wr = tid & 127, wh = tid >> 7;
    const int* w2row = w2 + ((long)e * H_ + h0 + wr) * (I_ / 2) + wh * 8;
    long srow = ((long)e * H_ + h0 + wr) * (I_ / GS);

    float acc[2][4][4];
#pragma unroll
    for (int b = 0; b < 2; b++)
#pragma unroll
        for (int c = 0; c < 4; c++)
#pragma unroll
            for (int d = 0; d < 4; d++) acc[b][c][d] = 0.f;

    for (int kc = 0; kc < I_ / 32; kc++) {
        __syncthreads();
        {
            uint4 v = *(const uint4*)((const __nv_bfloat16*)g_gbuf + grow +
                                      kc * 32 + gseg * 8);
            *(uint4*)&Gs[gslot * RS + gseg * 4] = v;
        }
        {
            int s = w2s[srow + kc];
            unsigned sb = (unsigned)(s << 7) * 0x10001u;
            __nv_bfloat162 sc = *(__nv_bfloat162*)&sb;
            int4 v0 = *(const int4*)(w2row + kc * 16);
            int4 v1 = *(const int4*)(w2row + kc * 16 + 4);
            uint4 o0, o1;
            {
                __nv_bfloat162 r;
                unsigned lw;
                lw = LUT[v0.x & 255]; r = __hmul2(*(__nv_bfloat162*)&lw, sc); o0.x = *(unsigned*)&r;
                lw = LUT[v0.y & 255]; r = __hmul2(*(__nv_bfloat162*)&lw, sc); o0.y = *(unsigned*)&r;
                lw = LUT[v0.z & 255]; r = __hmul2(*(__nv_bfloat162*)&lw, sc); o0.z = *(unsigned*)&r;
                lw = LUT[v0.w & 255]; r = __hmul2(*(__nv_bfloat162*)&lw, sc); o0.w = *(unsigned*)&r;
                lw = LUT[v1.x & 255]; r = __hmul2(*(__nv_bfloat162*)&lw, sc); o1.x = *(unsigned*)&r;
                lw = LUT[v1.y & 255]; r = __hmul2(*(__nv_bfloat162*)&lw, sc); o1.y = *(unsigned*)&r;
                lw = LUT[v1.z & 255]; r = __hmul2(*(__nv_bfloat162*)&lw, sc); o1.z = *(unsigned*)&r;
                lw = LUT[v1.w & 255]; r = __hmul2(*(__nv_bfloat162*)&lw, sc); o1.w = *(unsigned*)&r;
            }
            *(uint4*)&Ws[wr * RS + wh * 8] = o0;
            *(uint4*)&Ws[wr * RS + wh * 8 + 4] = o1;
        }
        __syncthreads();

#pragma unroll
        for (int kst = 0; kst < 2; kst++) {
            unsigned b[2][4];
#pragma unroll
            for (int p = 0; p < 2; p++)
                ldsm4(b[p][0], b[p][1], b[p][2], b[p][3],
                      &Gs[(wn * 32 + p * 16 + lrow) * RS + kst * 8 + lword]);
#pragma unroll
            for (int mt = 0; mt < 2; mt++) {
                unsigned a0, a1, a2, a3;
                ldsm4(a0, a1, a2, a3,
                      &Ws[(wm * 32 + mt * 16 + lrow) * RS + kst * 8 + lword]);
#pragma unroll
                for (int nt = 0; nt < 4; nt++)
                    mma16816(acc[mt][nt], a0, a1, a2, a3,
                             b[nt >> 1][nt & 1], b[nt >> 1][2 + (nt & 1)]);
            }
        }
    }

    int bf32 = g_b2f32;
    const float* bpf = (const float*)g_w2b + (long)e * H_;
    const __nv_bfloat16* bph = (const __nv_bfloat16*)g_w2b + (long)e * H_;
#pragma unroll
    for (int mt = 0; mt < 2; mt++) {
#pragma unroll
        for (int rr = 0; rr < 2; rr++) {
            int h = h0 + wm * 32 + mt * 16 + gq + rr * 8;
            float bv = bf32 ? bpf[h] : __bfloat162float(bph[h]);
#pragma unroll
            for (int nt = 0; nt < 4; nt++) {
#pragma unroll
                for (int cc = 0; cc < 2; cc++) {
                    int slot = bn0 + wn * 32 + nt * 8 + 2 * cq + cc;
                    if (slot >= cnt) continue;
                    int entry = sent[slot - bn0];
                    int t = entry >> 1, kk = entry & 1;
                    float o = rb(acc[mt][nt][rr * 2 + cc]);
                    o = rb(o + bv);
                    g_oslot[((size_t)(t * 2 + kk)) * H_ + h] = o;
                }
            }
        }
    }
}

// ---------------- K4: weighted combine ----------------
__global__ void __launch_bounds__(256) k_comb(void* __restrict__ out) {
    int idx = blockIdx.x * 256 + threadIdx.x;
    if (idx >= T_ * H_) return;
    int t = idx / H_;
    int h = idx - t * H_;
    float r = g_wts[t * 2 + 0] * g_oslot[(size_t)(t * 2 + 0) * H_ + h]
            + g_wts[t * 2 + 1] * g_oslot[(size_t)(t * 2 + 1) * H_ + h];
    __nv_bfloat16 v = __float2bfloat16(r);
    if (g_xf32) ((float*)out)[idx] = __bfloat162float(v);
    else        ((__nv_bfloat16*)out)[idx] = v;
}

// ---------------- host ----------------
extern "C" void kernel_launch(void* const* d_in, const int* in_sizes, int n_in,
                              void* d_out, int out_size) {
    const void *p2m0 = 0, *p2m1 = 0, *p16k0 = 0, *p16k1 = 0;
    const int *w1 = 0, *w3 = 0, *w2 = 0, *w13s = 0;
    const void *w13b = 0;

    int big_idx[3] = {-1, -1, -1};
    int nbig = 0, n2m = 0, n16k = 0;
    for (int i = 0; i < n_in; i++) {
        int s = in_sizes[i];
        if (s == 2097152) {
            if (n2m == 0) p2m0 = d_in[i]; else p2m1 = d_in[i];
            n2m++;
        } else if (s == 16384) {
            if (n16k == 0) p16k0 = d_in[i]; else p16k1 = d_in[i];
            n16k++;
        } else if (s == 4194304) {
            w13s = (const int*)d_in[i];
        } else if (s == 65536) {
            w13b = d_in[i];
        } else if (s == 33554432) {
            if (nbig < 3) big_idx[nbig] = i;
            nbig++;
        }
    }
    bool contiguous = (nbig == 3 && big_idx[1] == big_idx[0] + 1 &&
                       big_idx[2] == big_idx[1] + 1);
    w1 = (const int*)d_in[big_idx[0]];
    if (contiguous) {           // dict order: w1, w3, w2
        w3 = (const int*)d_in[big_idx[1]];
        w2 = (const int*)d_in[big_idx[2]];
    } else {                    // alphabetical: w1, w2, w3
        w2 = (const int*)d_in[big_idx[1]];
        w3 = (const int*)d_in[big_idx[2]];
    }

    k_probe<<<1, 256>>>(p2m0, p2m1, p16k0, p16k1, w13b);
    k_gate<<<T_ / 8, 256>>>();
    k_up<<<dim3(I_ / 128, T_ / 64, E_), 256>>>(w1, w3, w13s, w13b);
    k_down<<<dim3(H_ / 128, T_ / 64, E_), 256>>>(w2);
    k_comb<<<(T_ * H_ + 255) / 256, 256>>>(d_out);
}

// round 17
// speedup vs baseline: 3.9272x; 1.1111x over previous
#include <cuda_runtime.h>
#include <cuda_bf16.h>

#define T_  1024
#define H_  2048
#define I_  4096
#define E_  8
#define GS  32
#define RS  20   // words per 32-bf16 SMEM row (16 data + 4 pad), 16B-aligned rows

// ---------------- static device scratch ----------------
__device__ __nv_bfloat16 g_gbuf[(size_t)E_ * T_ * I_];
__device__ float g_oslot[(size_t)T_ * 2 * H_];
__device__ float g_wts[T_ * 2];
__device__ int   g_cnt[E_];
__device__ int   g_entries[E_ * T_];

__device__ const void* g_x;
__device__ const int*  g_w2s;
__device__ const float* g_gw;
__device__ const void* g_w2b;
__device__ int g_xf32, g_b13f32, g_b2f32;

__device__ int looks_f32(const unsigned* u, int n) {
    int small = 0;
    for (int i = 0; i < n; i++) {
        unsigned e = (u[i] >> 7) & 0xFF;
        if (e < 64) small++;
    }
    return small > (n >> 4);
}

__device__ __forceinline__ float rb(float v) {
    return __bfloat162float(__float2bfloat16(v));
}

__device__ __forceinline__ void mma16816(float* d, unsigned a0, unsigned a1,
                                         unsigned a2, unsigned a3,
                                         unsigned b0, unsigned b1) {
    asm volatile(
        "mma.sync.aligned.m16n8k16.row.col.f32.bf16.bf16.f32 "
        "{%0,%1,%2,%3},{%4,%5,%6,%7},{%8,%9},{%0,%1,%2,%3};"
        : "+f"(d[0]), "+f"(d[1]), "+f"(d[2]), "+f"(d[3])
        : "r"(a0), "r"(a1), "r"(a2), "r"(a3), "r"(b0), "r"(b1));
}

__device__ __forceinline__ void ldsm4(unsigned& r0, unsigned& r1,
                                      unsigned& r2, unsigned& r3,
                                      const unsigned* p) {
    unsigned addr = (unsigned)__cvta_generic_to_shared(p);
    asm volatile("ldmatrix.sync.aligned.m8n8.x4.shared.b16 {%0,%1,%2,%3},[%4];"
                 : "=r"(r0), "=r"(r1), "=r"(r2), "=r"(r3) : "r"(addr));
}

// ---------------- PRMT fp4 dequant (exact; no SMEM LUT) ----------------
// pack low bytes of 4 int32 (each int32 = 1 byte = 2 fp4 nibbles) into one u32
__device__ __forceinline__ unsigned pack4(int4 v) {
    unsigned p01, p23, r;
    asm("prmt.b32 %0,%1,%2,%3;" : "=r"(p01) : "r"((unsigned)v.x), "r"((unsigned)v.y), "r"(0x0040u));
    asm("prmt.b32 %0,%1,%2,%3;" : "=r"(p23) : "r"((unsigned)v.z), "r"((unsigned)v.w), "r"(0x0040u));
    asm("prmt.b32 %0,%1,%2,%3;" : "=r"(r) : "r"(p01), "r"(p23), "r"(0x5410u));
    return r;
}

// expand 8 nibbles (u32) -> 8 bf16 (uint4 of bf16x2), scaled by scw (bf16x2 2^(s-127))
// e2m1 magnitudes 0,.5,1,1.5,2,3,4,6 -> bf16 hi bytes {00,3F,3F,3F,40,40,40,40},
// lo bytes {00,00,80,C0,00,40,80,C0}; sign bit OR'd into bit15 of each half.
__device__ __forceinline__ uint4 dq8(unsigned B, unsigned scw) {
    __nv_bfloat162 sc = *(__nv_bfloat162*)&scw;
    unsigned mags = B & 0x77777777u;
    unsigned m23 = mags >> 16;
    unsigned hit_a = 0x3F3F3F00u, hit_b = 0x40404040u;
    unsigned lot_a = 0xC0800000u, lot_b = 0xC0804000u;
    unsigned HB01, LB01, HB23, LB23, w0, w1, w2, w3;
    asm("prmt.b32 %0,%1,%2,%3;" : "=r"(HB01) : "r"(hit_a), "r"(hit_b), "r"(mags));
    asm("prmt.b32 %0,%1,%2,%3;" : "=r"(LB01) : "r"(lot_a), "r"(lot_b), "r"(mags));
    asm("prmt.b32 %0,%1,%2,%3;" : "=r"(HB23) : "r"(hit_a), "r"(hit_b), "r"(m23));
    asm("prmt.b32 %0,%1,%2,%3;" : "=r"(LB23) : "r"(lot_a), "r"(lot_b), "r"(m23));
    asm("prmt.b32 %0,%1,%2,%3;" : "=r"(w0) : "r"(LB01), "r"(HB01), "r"(0x5140u));
    asm("prmt.b32 %0,%1,%2,%3;" : "=r"(w1) : "r"(LB01), "r"(HB01), "r"(0x7362u));
    asm("prmt.b32 %0,%1,%2,%3;" : "=r"(w2) : "r"(LB23), "r"(HB23), "r"(0x5140u));
    asm("prmt.b32 %0,%1,%2,%3;" : "=r"(w3) : "r"(LB23), "r"(HB23), "r"(0x7362u));
    w0 |= ((B & 0x8u) << 12) | ((B & 0x80u) << 24);
    w1 |= ((B & 0x800u) << 4) | ((B & 0x8000u) << 16);
    w2 |= ((B & 0x80000u) >> 4) | ((B & 0x800000u) << 8);
    w3 |= ((B & 0x8000000u) >> 12) | (B & 0x80000000u);
    __nv_bfloat162 r0 = __hmul2(*(__nv_bfloat162*)&w0, sc);
    __nv_bfloat162 r1 = __hmul2(*(__nv_bfloat162*)&w1, sc);
    __nv_bfloat162 r2 = __hmul2(*(__nv_bfloat162*)&w2, sc);
    __nv_bfloat162 r3 = __hmul2(*(__nv_bfloat162*)&w3, sc);
    uint4 o;
    o.x = *(unsigned*)&r0; o.y = *(unsigned*)&r1;
    o.z = *(unsigned*)&r2; o.w = *(unsigned*)&r3;
    return o;
}

// ---------------- K-1: probe ----------------
__global__ void k_probe(const void* a2m0, const void* a2m1,
                        const void* a16k0, const void* a16k1,
                        const void* w13b) {
    if (threadIdx.x != 0) return;
    const unsigned* u = (const unsigned*)a2m0;
    bool allsmall = true;
    for (int i = 0; i < 4096; i++) if (u[i] >= 128u) { allsmall = false; break; }
    const void* xptr; const void* w2sptr;
    if (allsmall) { w2sptr = a2m0; xptr = a2m1; }
    else          { xptr = a2m0;  w2sptr = a2m1; }
    g_x = xptr; g_w2s = (const int*)w2sptr;
    const float* f = (const float*)a16k0;
    bool big = false;
    for (int i = 0; i < 4096; i++) if (fabsf(f[i]) >= 1.f) { big = true; break; }
    const void* gwp; const void* w2bp;
    if (big) { w2bp = a16k0; gwp = a16k1; }
    else     { gwp = a16k0;  w2bp = a16k1; }
    g_gw = (const float*)gwp; g_w2b = w2bp;
    g_xf32   = looks_f32((const unsigned*)xptr, 256);
    g_b13f32 = looks_f32((const unsigned*)w13b, 256);
    g_b2f32  = looks_f32((const unsigned*)w2bp, 256);
    for (int e = 0; e < E_; e++) g_cnt[e] = 0;
}

// ---------------- K1: gating ----------------
__global__ void __launch_bounds__(256) k_gate() {
    const float* gw = g_gw;
    int xf = g_xf32;
    const float* xf32 = (const float*)g_x;
    const __nv_bfloat16* xb = (const __nv_bfloat16*)g_x;
    int warp = threadIdx.x >> 5, lane = threadIdx.x & 31;
    int t = blockIdx.x * 8 + warp;
    float acc[E_];
#pragma unroll
    for (int e = 0; e < E_; e++) acc[e] = 0.f;
    for (int h = lane; h < H_; h += 32) {
        float xv = xf ? xf32[(size_t)t * H_ + h]
                      : __bfloat162float(xb[(size_t)t * H_ + h]);
#pragma unroll
        for (int e = 0; e < E_; e++) acc[e] += xv * gw[e * H_ + h];
    }
#pragma unroll
    for (int e = 0; e < E_; e++) {
#pragma unroll
        for (int off = 16; off > 0; off >>= 1)
            acc[e] += __shfl_xor_sync(0xffffffffu, acc[e], off);
    }
    if (lane == 0) {
        float m = acc[0];
#pragma unroll
        for (int e = 1; e < E_; e++) m = fmaxf(m, acc[e]);
        float p[E_], s = 0.f;
#pragma unroll
        for (int e = 0; e < E_; e++) { p[e] = expf(acc[e] - m); s += p[e]; }
#pragma unroll
        for (int e = 0; e < E_; e++) p[e] /= s;
        int i0 = 0; float p0v = p[0];
#pragma unroll
        for (int e = 1; e < E_; e++) if (p[e] > p0v) { p0v = p[e]; i0 = e; }
        int i1 = -1; float p1v = -1.f;
#pragma unroll
        for (int e = 0; e < E_; e++) {
            if (e == i0) continue;
            if (p[e] > p1v) { p1v = p[e]; i1 = e; }
        }
        float ws = p0v + p1v;
        g_wts[t * 2 + 0] = p0v / ws;
        g_wts[t * 2 + 1] = p1v / ws;
        int pos = atomicAdd(&g_cnt[i0], 1);
        g_entries[i0 * T_ + pos] = (t << 1);
        pos = atomicAdd(&g_cnt[i1], 1);
        g_entries[i1 * T_ + pos] = (t << 1) | 1;
    }
}

// ---------------- K2: up projection (HMMA + ldmatrix + PRMT dequant) ----------------
__global__ void __launch_bounds__(256) k_up(const int* __restrict__ w1,
                                            const int* __restrict__ w3,
                                            const int* __restrict__ w13s,
                                            const void* __restrict__ w13b) {
    int e = blockIdx.z;
    int cnt = g_cnt[e];
    int bn0 = blockIdx.y * 64;
    if (bn0 >= cnt) return;
    int i0 = blockIdx.x * 128;

    __shared__ __align__(16) unsigned W1s[128 * RS];
    __shared__ __align__(16) unsigned W3s[128 * RS];
    __shared__ __align__(16) unsigned Xs[64 * RS];
    __shared__ int stok[64];

    int tid = threadIdx.x;
    if (tid < 64) {
        int slot = bn0 + tid;
        stok[tid] = (slot < cnt) ? (g_entries[e * T_ + slot] >> 1) : -1;
    }
    __syncthreads();

    int xf = g_xf32;
    int lane = tid & 31, wid = tid >> 5;
    int wm = wid & 3, wn = wid >> 2;
    int gq = lane >> 2, cq = lane & 3;
    int lrow = (lane & 7) + ((lane >> 3) & 1) * 8;
    int lword = ((lane >> 4) & 1) * 4;

    int xslot = tid >> 2, xseg = tid & 3;
    int xt = stok[xslot];
    int wr = tid & 127, wh = tid >> 7;
    const int* w1row = w1 + ((long)e * I_ + i0 + wr) * (H_ / 2) + wh * 8;
    const int* w3row = w3 + ((long)e * I_ + i0 + wr) * (H_ / 2) + wh * 8;
    long s1row = ((long)e * 2 * I_ + i0 + wr) * (H_ / GS);
    long s3row = ((long)e * 2 * I_ + I_ + i0 + wr) * (H_ / GS);

    float acc[2][2][4][4];
#pragma unroll
    for (int a = 0; a < 2; a++)
#pragma unroll
        for (int b = 0; b < 2; b++)
#pragma unroll
            for (int c = 0; c < 4; c++)
#pragma unroll
                for (int d = 0; d < 4; d++) acc[a][b][c][d] = 0.f;

    for (int kc = 0; kc < H_ / 32; kc++) {
        __syncthreads();
        // ---- X stage ----
        {
            uint4 ov = make_uint4(0u, 0u, 0u, 0u);
            if (xt >= 0) {
                if (xf) {
                    const float* xp = (const float*)g_x + (size_t)xt * H_ +
                                      kc * 32 + xseg * 8;
                    float4 v0 = ((const float4*)xp)[0];
                    float4 v1 = ((const float4*)xp)[1];
                    __nv_bfloat162 p0 = __floats2bfloat162_rn(v0.x, v0.y);
                    __nv_bfloat162 p1 = __floats2bfloat162_rn(v0.z, v0.w);
                    __nv_bfloat162 p2 = __floats2bfloat162_rn(v1.x, v1.y);
                    __nv_bfloat162 p3 = __floats2bfloat162_rn(v1.z, v1.w);
                    ov.x = *(unsigned*)&p0; ov.y = *(unsigned*)&p1;
                    ov.z = *(unsigned*)&p2; ov.w = *(unsigned*)&p3;
                } else {
                    ov = *(const uint4*)((const __nv_bfloat16*)g_x +
                         (size_t)xt * H_ + kc * 32 + xseg * 8);
                }
            }
            *(uint4*)&Xs[xslot * RS + xseg * 4] = ov;
        }
        // ---- W1 / W3 stage (PRMT dequant, no LUT) ----
        {
            unsigned sc1 = (unsigned)(w13s[s1row + kc] << 7) * 0x10001u;
            int4 v0 = *(const int4*)(w1row + kc * 16);
            int4 v1 = *(const int4*)(w1row + kc * 16 + 4);
            uint4 o0 = dq8(pack4(v0), sc1);
            uint4 o1 = dq8(pack4(v1), sc1);
            *(uint4*)&W1s[wr * RS + wh * 8] = o0;
            *(uint4*)&W1s[wr * RS + wh * 8 + 4] = o1;

            unsigned sc3 = (unsigned)(w13s[s3row + kc] << 7) * 0x10001u;
            int4 q0 = *(const int4*)(w3row + kc * 16);
            int4 q1 = *(const int4*)(w3row + kc * 16 + 4);
            uint4 t0 = dq8(pack4(q0), sc3);
            uint4 t1 = dq8(pack4(q1), sc3);
            *(uint4*)&W3s[wr * RS + wh * 8] = t0;
            *(uint4*)&W3s[wr * RS + wh * 8 + 4] = t1;
        }
        __syncthreads();

        // ---- fragments + MMA ----
#pragma unroll
        for (int kst = 0; kst < 2; kst++) {
            unsigned b[2][4];
#pragma unroll
            for (int p = 0; p < 2; p++)
                ldsm4(b[p][0], b[p][1], b[p][2], b[p][3],
                      &Xs[(wn * 32 + p * 16 + lrow) * RS + kst * 8 + lword]);
#pragma unroll
            for (int mt = 0; mt < 2; mt++) {
                unsigned a0, a1, a2, a3;
                ldsm4(a0, a1, a2, a3,
                      &W1s[(wm * 32 + mt * 16 + lrow) * RS + kst * 8 + lword]);
#pragma unroll
                for (int nt = 0; nt < 4; nt++)
                    mma16816(acc[0][mt][nt], a0, a1, a2, a3,
                             b[nt >> 1][nt & 1], b[nt >> 1][2 + (nt & 1)]);
                unsigned c0, c1, c2, c3;
                ldsm4(c0, c1, c2, c3,
                      &W3s[(wm * 32 + mt * 16 + lrow) * RS + kst * 8 + lword]);
#pragma unroll
                for (int nt = 0; nt < 4; nt++)
                    mma16816(acc[1][mt][nt], c0, c1, c2, c3,
                             b[nt >> 1][nt & 1], b[nt >> 1][2 + (nt & 1)]);
            }
        }
    }

    // ---- epilogue (frozen numerics) ----
    int bf32 = g_b13f32;
    const float* bpf = (const float*)w13b + (long)e * 2 * I_;
    const __nv_bfloat16* bph = (const __nv_bfloat16*)w13b + (long)e * 2 * I_;
#pragma unroll
    for (int mt = 0; mt < 2; mt++) {
#pragma unroll
        for (int rr = 0; rr < 2; rr++) {
            int i = i0 + wm * 32 + mt * 16 + gq + rr * 8;
            float b1v = bf32 ? bpf[i]      : __bfloat162float(bph[i]);
            float b3v = bf32 ? bpf[I_ + i] : __bfloat162float(bph[I_ + i]);
#pragma unroll
            for (int nt = 0; nt < 4; nt++) {
#pragma unroll
                for (int cc = 0; cc < 2; cc++) {
                    int slot = bn0 + wn * 32 + nt * 8 + 2 * cq + cc;
                    if (slot >= cnt) continue;
                    float h1 = rb(acc[0][mt][nt][rr * 2 + cc]);
                    h1 = rb(h1 + b1v);
                    float h3 = rb(acc[1][mt][nt][rr * 2 + cc]);
                    h3 = rb(h3 + b3v);
                    float em  = rb(expf(-h1));
                    float den = rb(1.f + em);
                    float sg  = rb(1.f / den);
                    float sl  = rb(h1 * sg);
                    g_gbuf[((size_t)e * T_ + slot) * I_ + i] =
                        __float2bfloat16(sl * h3);
                }
            }
        }
    }
}

// ---------------- K3: down projection (HMMA + ldmatrix + PRMT dequant) ----------------
__global__ void __launch_bounds__(256) k_down(const int* __restrict__ w2) {
    const int* w2s = g_w2s;
    int e = blockIdx.z;
    int cnt = g_cnt[e];
    int bn0 = blockIdx.y * 64;
    if (bn0 >= cnt) return;
    int h0 = blockIdx.x * 128;

    __shared__ __align__(16) unsigned Ws[128 * RS];
    __shared__ __align__(16) unsigned Gs[64 * RS];
    __shared__ int sent[64];

    int tid = threadIdx.x;
    if (tid < 64) {
        int slot = bn0 + tid;
        sent[tid] = (slot < cnt) ? g_entries[e * T_ + slot] : -1;
    }
    __syncthreads();

    int lane = tid & 31, wid = tid >> 5;
    int wm = wid & 3, wn = wid >> 2;
    int gq = lane >> 2, cq = lane & 3;
    int lrow = (lane & 7) + ((lane >> 3) & 1) * 8;
    int lword = ((lane >> 4) & 1) * 4;

    int gslot = tid >> 2, gseg = tid & 3;
    size_t grow = ((size_t)e * T_ + bn0 + gslot) * I_;
    int wr = tid & 127, wh = tid >> 7;
    const int* w2row = w2 + ((long)e * H_ + h0 + wr) * (I_ / 2) + wh * 8;
    long srow = ((long)e * H_ + h0 + wr) * (I_ / GS);

    float acc[2][4][4];
#pragma unroll
    for (int b = 0; b < 2; b++)
#pragma unroll
        for (int c = 0; c < 4; c++)
#pragma unroll
            for (int d = 0; d < 4; d++) acc[b][c][d] = 0.f;

    for (int kc = 0; kc < I_ / 32; kc++) {
        __syncthreads();
        {
            uint4 v = *(const uint4*)((const __nv_bfloat16*)g_gbuf + grow +
                                      kc * 32 + gseg * 8);
            *(uint4*)&Gs[gslot * RS + gseg * 4] = v;
        }
        {
            unsigned sc = (unsigned)(w2s[srow + kc] << 7) * 0x10001u;
            int4 v0 = *(const int4*)(w2row + kc * 16);
            int4 v1 = *(const int4*)(w2row + kc * 16 + 4);
            uint4 o0 = dq8(pack4(v0), sc);
            uint4 o1 = dq8(pack4(v1), sc);
            *(uint4*)&Ws[wr * RS + wh * 8] = o0;
            *(uint4*)&Ws[wr * RS + wh * 8 + 4] = o1;
        }
        __syncthreads();

#pragma unroll
        for (int kst = 0; kst < 2; kst++) {
            unsigned b[2][4];
#pragma unroll
            for (int p = 0; p < 2; p++)
                ldsm4(b[p][0], b[p][1], b[p][2], b[p][3],
                      &Gs[(wn * 32 + p * 16 + lrow) * RS + kst * 8 + lword]);
#pragma unroll
            for (int mt = 0; mt < 2; mt++) {
                unsigned a0, a1, a2, a3;
                ldsm4(a0, a1, a2, a3,
                      &Ws[(wm * 32 + mt * 16 + lrow) * RS + kst * 8 + lword]);
#pragma unroll
                for (int nt = 0; nt < 4; nt++)
                    mma16816(acc[mt][nt], a0, a1, a2, a3,
                             b[nt >> 1][nt & 1], b[nt >> 1][2 + (nt & 1)]);
            }
        }
    }

    int bf32 = g_b2f32;
    const float* bpf = (const float*)g_w2b + (long)e * H_;
    const __nv_bfloat16* bph = (const __nv_bfloat16*)g_w2b + (long)e * H_;
#pragma unroll
    for (int mt = 0; mt < 2; mt++) {
#pragma unroll
        for (int rr = 0; rr < 2; rr++) {
            int h = h0 + wm * 32 + mt * 16 + gq + rr * 8;
            float bv = bf32 ? bpf[h] : __bfloat162float(bph[h]);
#pragma unroll
            for (int nt = 0; nt < 4; nt++) {
#pragma unroll
                for (int cc = 0; cc < 2; cc++) {
                    int slot = bn0 + wn * 32 + nt * 8 + 2 * cq + cc;
                    if (slot >= cnt) continue;
                    int entry = sent[slot - bn0];
                    int t = entry >> 1, kk = entry & 1;
                    float o = rb(acc[mt][nt][rr * 2 + cc]);
                    o = rb(o + bv);
                    g_oslot[((size_t)(t * 2 + kk)) * H_ + h] = o;
                }
            }
        }
    }
}

// ---------------- K4: weighted combine ----------------
__global__ void __launch_bounds__(256) k_comb(void* __restrict__ out) {
    int idx = blockIdx.x * 256 + threadIdx.x;
    if (idx >= T_ * H_) return;
    int t = idx / H_;
    int h = idx - t * H_;
    float r = g_wts[t * 2 + 0] * g_oslot[(size_t)(t * 2 + 0) * H_ + h]
            + g_wts[t * 2 + 1] * g_oslot[(size_t)(t * 2 + 1) * H_ + h];
    __nv_bfloat16 v = __float2bfloat16(r);
    if (g_xf32) ((float*)out)[idx] = __bfloat162float(v);
    else        ((__nv_bfloat16*)out)[idx] = v;
}

// ---------------- host ----------------
extern "C" void kernel_launch(void* const* d_in, const int* in_sizes, int n_in,
                              void* d_out, int out_size) {
    const void *p2m0 = 0, *p2m1 = 0, *p16k0 = 0, *p16k1 = 0;
    const int *w1 = 0, *w3 = 0, *w2 = 0, *w13s = 0;
    const void *w13b = 0;

    int big_idx[3] = {-1, -1, -1};
    int nbig = 0, n2m = 0, n16k = 0;
    for (int i = 0; i < n_in; i++) {
        int s = in_sizes[i];
        if (s == 2097152) {
            if (n2m == 0) p2m0 = d_in[i]; else p2m1 = d_in[i];
            n2m++;
        } else if (s == 16384) {
            if (n16k == 0) p16k0 = d_in[i]; else p16k1 = d_in[i];
            n16k++;
        } else if (s == 4194304) {
            w13s = (const int*)d_in[i];
        } else if (s == 65536) {
            w13b = d_in[i];
        } else if (s == 33554432) {
            if (nbig < 3) big_idx[nbig] = i;
            nbig++;
        }
    }
    bool contiguous = (nbig == 3 && big_idx[1] == big_idx[0] + 1 &&
                       big_idx[2] == big_idx[1] + 1);
    w1 = (const int*)d_in[big_idx[0]];
    if (contiguous) {           // dict order: w1, w3, w2
        w3 = (const int*)d_in[big_idx[1]];
        w2 = (const int*)d_in[big_idx[2]];
    } else {                    // alphabetical: w1, w2, w3
        w2 = (const int*)d_in[big_idx[1]];
        w3 = (const int*)d_in[big_idx[2]];
    }

    k_probe<<<1, 32>>>(p2m0, p2m1, p16k0, p16k1, w13b);
    k_gate<<<T_ / 8, 256>>>();
    k_up<<<dim3(I_ / 128, T_ / 64, E_), 256>>>(w1, w3, w13s, w13b);
    k_down<<<dim3(H_ / 128, T_ / 64, E_), 256>>>(w2);
    k_comb<<<(T_ * H_ + 255) / 256, 256>>>(d_out);
}